// round 3
// baseline (speedup 1.0000x reference)
#include <cuda_runtime.h>
#include <math.h>

#define C 21
#define FG 20
#define TOPK 512
#define CAND_STRIDE 262144
#define SORTCAP 8192
#define HBINS 16384
#define DETS 100
#define SCORE_TH 0.05f
#define NMS_TH 0.5f
#define BBOX_CLIPV 4.135166556742356f

// ---------------- static device scratch ------------------------------------
__device__ unsigned int       g_hist[FG * HBINS];         // 1.3 MB
__device__ int                g_cnt[FG];
__device__ int                g_selcnt[FG];
__device__ int                g_cut[FG];
__device__ unsigned long long g_cand[FG * CAND_STRIDE];
__device__ unsigned long long g_sel[FG * SORTCAP];
__device__ float              g_vals[FG * TOPK];
__device__ int                g_keep[FG * TOPK];
__device__ float              g_obox[FG * TOPK * 7];
__device__ float              g_geo[FG * 7 * TOPK];
__device__ unsigned int       g_ov[FG * 16 * TOPK];
__device__ unsigned long long g_top[FG * 128];
__device__ int                g_topn[FG];
__device__ unsigned long long g_fill[128];
__device__ int                g_filln;

// ---------------- K0: zero hist + counters ---------------------------------
__global__ void zero_kernel() {
    int i = blockIdx.x * blockDim.x + threadIdx.x;
    const int total = FG * HBINS;
    for (; i < total; i += gridDim.x * blockDim.x) g_hist[i] = 0u;
    if (blockIdx.x == 0 && threadIdx.x < FG) {
        g_cnt[threadIdx.x] = 0;
        g_selcnt[threadIdx.x] = 0;
    }
}

// ---------------- K1: softmax + warp-aggregated compaction ------------------
__global__ void score_kernel(const float* __restrict__ logits, int N) {
    __shared__ float sl[256 * C];
    int base = blockIdx.x * 256;
    int tid = threadIdx.x;
    int lane = tid & 31;

    // staged, vectorized load: 256*21 floats = 1344 float4
    const float4* src = (const float4*)(logits + (size_t)base * C);
    float4* dst = (float4*)sl;
    for (int i = tid; i < 256 * C / 4; i += 256) dst[i] = src[i];
    __syncthreads();

    int row = base + tid;
    float e[C];
    float m = sl[tid * C];
#pragma unroll
    for (int j = 1; j < C; j++) m = fmaxf(m, sl[tid * C + j]);
    float s = 0.f;
#pragma unroll
    for (int j = 0; j < C; j++) { e[j] = __expf(sl[tid * C + j] - m); s += e[j]; }
    float inv = 1.0f / s;

#pragma unroll
    for (int c = 1; c < C; c++) {
        float p = e[c] * inv;
        bool q = p > SCORE_TH;
        unsigned int mask = __ballot_sync(0xFFFFFFFFu, q);
        if (mask) {
            int cl = c - 1;
            int leader = __ffs(mask) - 1;
            int base2 = 0;
            if (lane == leader) base2 = atomicAdd(&g_cnt[cl], __popc(mask));
            base2 = __shfl_sync(0xFFFFFFFFu, base2, leader);
            if (q) {
                unsigned int bits = __float_as_uint(p);
                atomicAdd(&g_hist[cl * HBINS + (bits >> 16)], 1u);
                int pos = base2 + __popc(mask & ((1u << lane) - 1u));
                g_cand[cl * CAND_STRIDE + pos] =
                    ((unsigned long long)bits << 32) |
                    (unsigned long long)(0xFFFFFFFFu - (unsigned int)row);
            }
        }
    }
}

// ---------------- K2: per-class cutoff bin for rank-512 ---------------------
__global__ void cutoff_kernel() {
    int c = blockIdx.x;
    __shared__ unsigned int chunk[256];
    const unsigned int* h = &g_hist[c * HBINS];
    int t = threadIdx.x;
    unsigned int sum = 0;
    for (int b = 0; b < 64; b++) sum += h[t * 64 + b];
    chunk[t] = sum;
    __syncthreads();
    if (t == 0) {
        unsigned int cum = 0;
        int B = 0;
        for (int ck = 255; ck >= 0; ck--) {
            if (cum + chunk[ck] >= TOPK) {
                for (int b = ck * 64 + 63; b >= ck * 64; b--) {
                    cum += h[b];
                    if (cum >= TOPK) { B = b; break; }
                }
                break;
            }
            cum += chunk[ck];
        }
        g_cut[c] = B;
    }
}

// ---------------- K2b: full-chip candidate filter ---------------------------
__global__ void filter_kernel() {
    int c = blockIdx.y;
    int cnt = g_cnt[c];
    unsigned int B = (unsigned int)g_cut[c];
    int chunk = (cnt + gridDim.x - 1) / gridDim.x;
    int lo = blockIdx.x * chunk;
    int hi = min(cnt, lo + chunk);
    const unsigned long long* cand = &g_cand[c * CAND_STRIDE];
    for (int i = lo + threadIdx.x; i < hi; i += blockDim.x) {
        unsigned long long k = cand[i];
        if ((unsigned int)(k >> 48) >= B) {
            int p = atomicAdd(&g_selcnt[c], 1);
            if (p < SORTCAP) g_sel[c * SORTCAP + p] = k;
        }
    }
}

// ---------------- K3a: bitonic sort + decode + geometry ---------------------
__global__ void select_kernel(const float* __restrict__ breg,
                              const float* __restrict__ props) {
    extern __shared__ unsigned long long skey[];
    int c = blockIdx.x, tid = threadIdx.x;
    int m = min(g_selcnt[c], SORTCAP);
    int n = 512;
    while (n < m) n <<= 1;
    for (int i = tid; i < n; i += 512)
        skey[i] = (i < m) ? g_sel[c * SORTCAP + i] : 0ULL;
    __syncthreads();

    for (int k = 2; k <= n; k <<= 1) {
        for (int j = k >> 1; j > 0; j >>= 1) {
            for (int i = tid; i < n; i += 512) {
                int ixj = i ^ j;
                if (ixj > i) {
                    unsigned long long a = skey[i], b = skey[ixj];
                    bool desc = ((i & k) == 0);
                    if (desc ? (a < b) : (a > b)) { skey[i] = b; skey[ixj] = a; }
                }
            }
            __syncthreads();
        }
    }

    unsigned long long k0 = skey[tid];
    float score = __uint_as_float((unsigned int)(k0 >> 32));
    int row = (int)(0xFFFFFFFFu - (unsigned int)(k0 & 0xFFFFFFFFu));
    if (!(score > SCORE_TH)) row = 0;

    const float* pr = props + (size_t)row * 7;
    const float* d = breg + (size_t)row * (C * 7) + (c + 1) * 7;
    float px = pr[0], py = pr[1], pzb = pr[2];
    float psx = pr[3], psy = pr[4], psz = pr[5], pry = pr[6];
    float pcz = pzb + psz * 0.5f;
    float cx = px + (d[0] / 10.0f) * psx;
    float cy = py + (d[1] / 10.0f) * psy;
    float cz = pcz + (d[2] / 10.0f) * psz;
    float sx = psx * expf(fminf(d[3] / 5.0f, BBOX_CLIPV));
    float sy = psy * expf(fminf(d[4] / 5.0f, BBOX_CLIPV));
    float sz = psz * expf(fminf(d[5] / 5.0f, BBOX_CLIPV));
    float ry = pry + d[6];
    float zb = cz - sz * 0.5f;

    float* ob = &g_obox[(c * TOPK + tid) * 7];
    ob[0] = cx; ob[1] = cy; ob[2] = zb; ob[3] = sx;
    ob[4] = sy; ob[5] = sz; ob[6] = ry;
    g_vals[c * TOPK + tid] = score;

    float* gg = &g_geo[c * 7 * TOPK];
    gg[0 * TOPK + tid] = cx - sx * 0.5f;
    gg[1 * TOPK + tid] = cx + sx * 0.5f;
    gg[2 * TOPK + tid] = cy - sy * 0.5f;
    gg[3 * TOPK + tid] = cy + sy * 0.5f;
    gg[4 * TOPK + tid] = zb;
    gg[5 * TOPK + tid] = zb + sz;
    gg[6 * TOPK + tid] = sx * sy * sz;
}

// ---------------- K3b: IoU bit-matrix, division-free, full chip -------------
__global__ void iou_kernel() {
    __shared__ float sj[7][64];
    int c = blockIdx.y, g = blockIdx.x, tid = threadIdx.x;
    int jbase = g * 64;
    const float* gg = &g_geo[c * 7 * TOPK];
    for (int t = tid; t < 7 * 64; t += 512) {
        int k = t >> 6, jj = t & 63;
        sj[k][jj] = gg[k * TOPK + jbase + jj];
    }
    float xl = gg[0 * TOPK + tid], xh = gg[1 * TOPK + tid];
    float yl = gg[2 * TOPK + tid], yh = gg[3 * TOPK + tid];
    float zl = gg[4 * TOPK + tid], zh = gg[5 * TOPK + tid];
    float vo = gg[6 * TOPK + tid];
    __syncthreads();

#pragma unroll
    for (int w = 0; w < 2; w++) {
        unsigned int word = 0;
#pragma unroll
        for (int b = 0; b < 32; b++) {
            int j = w * 32 + b;
            float ox = fmaxf(fminf(xh, sj[1][j]) - fmaxf(xl, sj[0][j]), 0.f);
            float oy = fmaxf(fminf(yh, sj[3][j]) - fmaxf(yl, sj[2][j]), 0.f);
            float oz = fmaxf(fminf(zh, sj[5][j]) - fmaxf(zl, sj[4][j]), 0.f);
            float inter = ox * oy * oz;
            float denom = vo + sj[6][j] - inter + 1e-7f;
            word |= (inter > NMS_TH * denom ? 1u : 0u) << b;
        }
        g_ov[c * (16 * TOPK) + (g * 2 + w) * TOPK + tid] = word;
    }
}

// ---------------- K3c: serial NMS + kept compaction -------------------------
__global__ void nms_kernel() {
    __shared__ unsigned int sov[16 * TOPK];
    __shared__ unsigned int vmask[16];
    __shared__ unsigned int keepw[16];
    int c = blockIdx.x, tid = threadIdx.x;
    for (int i = tid; i < 16 * TOPK; i += 512) sov[i] = g_ov[c * (16 * TOPK) + i];
    int valid = g_vals[c * TOPK + tid] > SCORE_TH;
    unsigned int bal = __ballot_sync(0xFFFFFFFFu, valid);
    if ((tid & 31) == 0) vmask[tid >> 5] = bal;
    __syncthreads();

    if (tid < 32) {
        int lane = tid;
        unsigned int kw = 0;
        unsigned int vw = lane < 16 ? vmask[lane] : 0u;
        unsigned int cur = lane < 16 ? sov[lane * TOPK] : 0u;
        for (int i = 0; i < TOPK; i++) {
            unsigned int nxt = (lane < 16 && i < TOPK - 1) ? sov[lane * TOPK + i + 1] : 0u;
            int sup = __any_sync(0xFFFFFFFFu, (cur & kw) != 0u);
            if (lane == (i >> 5)) {
                unsigned int kk = ((vw >> (i & 31)) & 1u) & (unsigned int)(!sup);
                kw |= kk << (i & 31);
            }
            cur = nxt;
        }
        if (lane < 16) keepw[lane] = kw;
    }
    __syncthreads();

    int w = tid >> 5, b = tid & 31;
    int keep = (keepw[w] >> b) & 1;
    int flat = c * TOPK + tid;
    g_keep[flat] = keep;
    int rank = 0;
    for (int ww = 0; ww < w; ww++) rank += __popc(keepw[ww]);
    rank += __popc(keepw[w] & ((1u << b) - 1u));

    if (keep && rank < 128) {
        unsigned int ms = __float_as_uint(g_vals[flat]) | 0x80000000u;
        g_top[c * 128 + rank] =
            ((unsigned long long)ms << 32) |
            (unsigned long long)(0xFFFFFFFFu - (unsigned int)flat);
    }
    if (tid == TOPK - 1) g_topn[c] = min(rank + keep, 128);
    if (c == 0) {
        int nrank = tid - rank;
        if (!keep && nrank < 128) {
            unsigned int ms = ~__float_as_uint(-1e9f);
            g_fill[nrank] =
                ((unsigned long long)ms << 32) |
                (unsigned long long)(0xFFFFFFFFu - (unsigned int)flat);
        }
        if (tid == TOPK - 1) g_filln = min(TOPK - (rank + keep), 128);
    }
}

// ---------------- K4: global top-100 via 4096-key bitonic sort --------------
__global__ void final_kernel(float* __restrict__ out) {
    __shared__ unsigned long long keys[4096];
    int tid = threadIdx.x;
    const int SLOTS = FG * 128;
    for (int i = tid; i < 4096; i += 1024) {
        unsigned long long k = 0;
        if (i < SLOTS) {
            int c = i >> 7, r = i & 127;
            if (r < g_topn[c]) k = g_top[i];
        } else if (i < SLOTS + 128) {
            int r = i - SLOTS;
            if (r < g_filln) k = g_fill[r];
        }
        keys[i] = k;
    }
    __syncthreads();
    for (int k = 2; k <= 4096; k <<= 1) {
        for (int j = k >> 1; j > 0; j >>= 1) {
            for (int i = tid; i < 4096; i += 1024) {
                int ixj = i ^ j;
                if (ixj > i) {
                    unsigned long long a = keys[i], bb = keys[ixj];
                    bool desc = ((i & k) == 0);
                    if (desc ? (a < bb) : (a > bb)) { keys[i] = bb; keys[ixj] = a; }
                }
            }
            __syncthreads();
        }
    }
    if (tid < DETS) {
        unsigned long long k = keys[tid];
        int flat = (int)(0xFFFFFFFFu - (unsigned int)(k & 0xFFFFFFFFu));
        float* o = out + tid * 9;
        const float* bx = &g_obox[flat * 7];
#pragma unroll
        for (int q = 0; q < 7; q++) o[q] = bx[q];
        o[7] = g_keep[flat] ? g_vals[flat] : -1e9f;
        o[8] = (float)((flat >> 9) + 1);
    }
}

// ---------------- launcher --------------------------------------------------
extern "C" void kernel_launch(void* const* d_in, const int* in_sizes, int n_in,
                              void* d_out, int out_size) {
    const float* logits = (const float*)d_in[0];
    const float* breg   = (const float*)d_in[1];
    const float* props  = (const float*)d_in[2];
    int N = in_sizes[2] / 7;

    cudaFuncSetAttribute(select_kernel,
                         cudaFuncAttributeMaxDynamicSharedMemorySize, 65536);

    zero_kernel<<<160, 256>>>();
    score_kernel<<<(N + 255) / 256, 256>>>(logits, N);
    cutoff_kernel<<<FG, 256>>>();
    filter_kernel<<<dim3(16, FG), 256>>>();
    select_kernel<<<FG, 512, 65536>>>(breg, props);
    iou_kernel<<<dim3(8, FG), 512>>>();
    nms_kernel<<<FG, 512>>>();
    final_kernel<<<1, 1024>>>((float*)d_out);
}

// round 4
// speedup vs baseline: 1.5777x; 1.5777x over previous
#include <cuda_runtime.h>
#include <math.h>

#define C 21
#define FG 20
#define TOPK 512
#define SORTCAP 8192
#define HBINS 16384
#define DETS 100
#define SCORE_TH 0.05f
#define NMS_TH 0.5f
#define BBOX_CLIPV 4.135166556742356f

// ---------------- static device scratch ------------------------------------
__device__ unsigned int       g_hist[FG * HBINS];         // 1.3 MB
__device__ int                g_selcnt[FG];
__device__ int                g_cut[FG];
__device__ unsigned long long g_sel[FG * SORTCAP];
__device__ float              g_vals[FG * TOPK];
__device__ int                g_keep[FG * TOPK];
__device__ float              g_obox[FG * TOPK * 7];
__device__ float              g_geo[FG * 7 * TOPK];
__device__ unsigned int       g_ov[FG * 16 * TOPK];
__device__ unsigned long long g_top[FG * 128];
__device__ int                g_topn[FG];
__device__ unsigned long long g_fill[128];
__device__ int                g_filln;

// ---------------- K0: zero hist + counters ---------------------------------
__global__ void zero_kernel() {
    int i = blockIdx.x * blockDim.x + threadIdx.x;
    const int total = FG * HBINS;
    for (; i < total; i += gridDim.x * blockDim.x) g_hist[i] = 0u;
    if (blockIdx.x == 0 && threadIdx.x < FG) g_selcnt[threadIdx.x] = 0;
}

// ---------------- K1: pass 1 — softmax + histogram only ---------------------
__global__ void hist_kernel(const float* __restrict__ logits, int N) {
    __shared__ float sl[256 * C];
    int base = blockIdx.x * 256;
    int tid = threadIdx.x;

    const float4* src = (const float4*)(logits + (size_t)base * C);
    float4* dst = (float4*)sl;
    for (int i = tid; i < 256 * C / 4; i += 256) dst[i] = src[i];
    __syncthreads();

    float e[C];
    float m = sl[tid * C];
#pragma unroll
    for (int j = 1; j < C; j++) m = fmaxf(m, sl[tid * C + j]);
    float s = 0.f;
#pragma unroll
    for (int j = 0; j < C; j++) { e[j] = __expf(sl[tid * C + j] - m); s += e[j]; }
    float inv = 1.0f / s;
    float ts = SCORE_TH * s;

#pragma unroll
    for (int c = 1; c < C; c++) {
        if (e[c] > ts) {
            unsigned int bits = __float_as_uint(e[c] * inv);
            atomicAdd(&g_hist[(c - 1) * HBINS + (bits >> 16)], 1u);
        }
    }
}

// ---------------- K2: per-class cutoff bin for rank-512 ---------------------
__global__ void cutoff_kernel() {
    int c = blockIdx.x;
    __shared__ unsigned int chunk[512];
    const unsigned int* h = &g_hist[c * HBINS];
    int t = threadIdx.x;
    unsigned int sum = 0;
    for (int b = 0; b < 32; b++) sum += h[t * 32 + b];
    chunk[t] = sum;
    __syncthreads();
    if (t == 0) {
        unsigned int cum = 0;
        int B = 0;
        for (int ck = 511; ck >= 0; ck--) {
            if (cum + chunk[ck] >= TOPK) {
                for (int b = ck * 32 + 31; b >= ck * 32; b--) {
                    cum += h[b];
                    if (cum >= TOPK) { B = b; break; }
                }
                break;
            }
            cum += chunk[ck];
        }
        g_cut[c] = B;
    }
}

// ---------------- K3: pass 2 — recompute softmax, push survivors ------------
__global__ void collect_kernel(const float* __restrict__ logits, int N) {
    __shared__ float sl[256 * C];
    __shared__ int scut[FG];
    int base = blockIdx.x * 256;
    int tid = threadIdx.x;
    int lane = tid & 31;
    if (tid < FG) scut[tid] = g_cut[tid];

    const float4* src = (const float4*)(logits + (size_t)base * C);
    float4* dst = (float4*)sl;
    for (int i = tid; i < 256 * C / 4; i += 256) dst[i] = src[i];
    __syncthreads();

    int row = base + tid;
    float e[C];
    float m = sl[tid * C];
#pragma unroll
    for (int j = 1; j < C; j++) m = fmaxf(m, sl[tid * C + j]);
    float s = 0.f;
#pragma unroll
    for (int j = 0; j < C; j++) { e[j] = __expf(sl[tid * C + j] - m); s += e[j]; }
    float inv = 1.0f / s;
    float ts = SCORE_TH * s;

#pragma unroll
    for (int c = 1; c < C; c++) {
        int cl = c - 1;
        unsigned int bits = 0;
        bool q = false;
        if (e[c] > ts) {
            bits = __float_as_uint(e[c] * inv);
            q = (int)(bits >> 16) >= scut[cl];
        }
        unsigned int mask = __ballot_sync(0xFFFFFFFFu, q);
        if (mask) {
            int leader = __ffs(mask) - 1;
            int base2 = 0;
            if (lane == leader) base2 = atomicAdd(&g_selcnt[cl], __popc(mask));
            base2 = __shfl_sync(0xFFFFFFFFu, base2, leader);
            if (q) {
                int pos = base2 + __popc(mask & ((1u << lane) - 1u));
                if (pos < SORTCAP)
                    g_sel[cl * SORTCAP + pos] =
                        ((unsigned long long)bits << 32) |
                        (unsigned long long)(0xFFFFFFFFu - (unsigned int)row);
            }
        }
    }
}

// ---------------- K4: bitonic sort + decode + geometry ----------------------
__global__ void select_kernel(const float* __restrict__ breg,
                              const float* __restrict__ props) {
    extern __shared__ unsigned long long skey[];
    int c = blockIdx.x, tid = threadIdx.x;
    int m = min(g_selcnt[c], SORTCAP);
    int n = 512;
    while (n < m) n <<= 1;
    for (int i = tid; i < n; i += 512)
        skey[i] = (i < m) ? g_sel[c * SORTCAP + i] : 0ULL;
    __syncthreads();

    for (int k = 2; k <= n; k <<= 1) {
        for (int j = k >> 1; j > 0; j >>= 1) {
            for (int i = tid; i < n; i += 512) {
                int ixj = i ^ j;
                if (ixj > i) {
                    unsigned long long a = skey[i], b = skey[ixj];
                    bool desc = ((i & k) == 0);
                    if (desc ? (a < b) : (a > b)) { skey[i] = b; skey[ixj] = a; }
                }
            }
            __syncthreads();
        }
    }

    unsigned long long k0 = skey[tid];
    float score = __uint_as_float((unsigned int)(k0 >> 32));
    int row = (int)(0xFFFFFFFFu - (unsigned int)(k0 & 0xFFFFFFFFu));
    if (!(score > SCORE_TH)) row = 0;

    const float* pr = props + (size_t)row * 7;
    const float* d = breg + (size_t)row * (C * 7) + (c + 1) * 7;
    float px = pr[0], py = pr[1], pzb = pr[2];
    float psx = pr[3], psy = pr[4], psz = pr[5], pry = pr[6];
    float pcz = pzb + psz * 0.5f;
    float cx = px + (d[0] / 10.0f) * psx;
    float cy = py + (d[1] / 10.0f) * psy;
    float cz = pcz + (d[2] / 10.0f) * psz;
    float sx = psx * expf(fminf(d[3] / 5.0f, BBOX_CLIPV));
    float sy = psy * expf(fminf(d[4] / 5.0f, BBOX_CLIPV));
    float sz = psz * expf(fminf(d[5] / 5.0f, BBOX_CLIPV));
    float ry = pry + d[6];
    float zb = cz - sz * 0.5f;

    float* ob = &g_obox[(c * TOPK + tid) * 7];
    ob[0] = cx; ob[1] = cy; ob[2] = zb; ob[3] = sx;
    ob[4] = sy; ob[5] = sz; ob[6] = ry;
    g_vals[c * TOPK + tid] = score;

    float* gg = &g_geo[c * 7 * TOPK];
    gg[0 * TOPK + tid] = cx - sx * 0.5f;
    gg[1 * TOPK + tid] = cx + sx * 0.5f;
    gg[2 * TOPK + tid] = cy - sy * 0.5f;
    gg[3 * TOPK + tid] = cy + sy * 0.5f;
    gg[4 * TOPK + tid] = zb;
    gg[5 * TOPK + tid] = zb + sz;
    gg[6 * TOPK + tid] = sx * sy * sz;
}

// ---------------- K5: IoU bit-matrix, division-free, full chip --------------
__global__ void iou_kernel() {
    __shared__ float sj[7][64];
    int c = blockIdx.y, g = blockIdx.x, tid = threadIdx.x;
    int jbase = g * 64;
    const float* gg = &g_geo[c * 7 * TOPK];
    for (int t = tid; t < 7 * 64; t += 512) {
        int k = t >> 6, jj = t & 63;
        sj[k][jj] = gg[k * TOPK + jbase + jj];
    }
    float xl = gg[0 * TOPK + tid], xh = gg[1 * TOPK + tid];
    float yl = gg[2 * TOPK + tid], yh = gg[3 * TOPK + tid];
    float zl = gg[4 * TOPK + tid], zh = gg[5 * TOPK + tid];
    float vo = gg[6 * TOPK + tid];
    __syncthreads();

#pragma unroll
    for (int w = 0; w < 2; w++) {
        unsigned int word = 0;
#pragma unroll
        for (int b = 0; b < 32; b++) {
            int j = w * 32 + b;
            float ox = fmaxf(fminf(xh, sj[1][j]) - fmaxf(xl, sj[0][j]), 0.f);
            float oy = fmaxf(fminf(yh, sj[3][j]) - fmaxf(yl, sj[2][j]), 0.f);
            float oz = fmaxf(fminf(zh, sj[5][j]) - fmaxf(zl, sj[4][j]), 0.f);
            float inter = ox * oy * oz;
            float denom = vo + sj[6][j] - inter + 1e-7f;
            word |= (inter > NMS_TH * denom ? 1u : 0u) << b;
        }
        g_ov[c * (16 * TOPK) + (g * 2 + w) * TOPK + tid] = word;
    }
}

// ---------------- K6: serial NMS + kept compaction --------------------------
__global__ void nms_kernel() {
    __shared__ unsigned int sov[16 * TOPK];
    __shared__ unsigned int vmask[16];
    __shared__ unsigned int keepw[16];
    int c = blockIdx.x, tid = threadIdx.x;
    for (int i = tid; i < 16 * TOPK; i += 512) sov[i] = g_ov[c * (16 * TOPK) + i];
    int valid = g_vals[c * TOPK + tid] > SCORE_TH;
    unsigned int bal = __ballot_sync(0xFFFFFFFFu, valid);
    if ((tid & 31) == 0) vmask[tid >> 5] = bal;
    __syncthreads();

    if (tid < 32) {
        int lane = tid;
        unsigned int kw = 0;
        unsigned int vw = lane < 16 ? vmask[lane] : 0u;
        unsigned int cur = lane < 16 ? sov[lane * TOPK] : 0u;
        for (int i = 0; i < TOPK; i++) {
            unsigned int nxt = (lane < 16 && i < TOPK - 1) ? sov[lane * TOPK + i + 1] : 0u;
            int sup = __any_sync(0xFFFFFFFFu, (cur & kw) != 0u);
            if (lane == (i >> 5)) {
                unsigned int kk = ((vw >> (i & 31)) & 1u) & (unsigned int)(!sup);
                kw |= kk << (i & 31);
            }
            cur = nxt;
        }
        if (lane < 16) keepw[lane] = kw;
    }
    __syncthreads();

    int w = tid >> 5, b = tid & 31;
    int keep = (keepw[w] >> b) & 1;
    int flat = c * TOPK + tid;
    g_keep[flat] = keep;
    int rank = 0;
    for (int ww = 0; ww < w; ww++) rank += __popc(keepw[ww]);
    rank += __popc(keepw[w] & ((1u << b) - 1u));

    if (keep && rank < 128) {
        unsigned int ms = __float_as_uint(g_vals[flat]) | 0x80000000u;
        g_top[c * 128 + rank] =
            ((unsigned long long)ms << 32) |
            (unsigned long long)(0xFFFFFFFFu - (unsigned int)flat);
    }
    if (tid == TOPK - 1) g_topn[c] = min(rank + keep, 128);
    if (c == 0) {
        int nrank = tid - rank;
        if (!keep && nrank < 128) {
            unsigned int ms = ~__float_as_uint(-1e9f);
            g_fill[nrank] =
                ((unsigned long long)ms << 32) |
                (unsigned long long)(0xFFFFFFFFu - (unsigned int)flat);
        }
        if (tid == TOPK - 1) g_filln = min(TOPK - (rank + keep), 128);
    }
}

// ---------------- K7: global top-100 via 4096-key bitonic sort --------------
__global__ void final_kernel(float* __restrict__ out) {
    __shared__ unsigned long long keys[4096];
    int tid = threadIdx.x;
    const int SLOTS = FG * 128;
    for (int i = tid; i < 4096; i += 1024) {
        unsigned long long k = 0;
        if (i < SLOTS) {
            int c = i >> 7, r = i & 127;
            if (r < g_topn[c]) k = g_top[i];
        } else if (i < SLOTS + 128) {
            int r = i - SLOTS;
            if (r < g_filln) k = g_fill[r];
        }
        keys[i] = k;
    }
    __syncthreads();
    for (int k = 2; k <= 4096; k <<= 1) {
        for (int j = k >> 1; j > 0; j >>= 1) {
            for (int i = tid; i < 4096; i += 1024) {
                int ixj = i ^ j;
                if (ixj > i) {
                    unsigned long long a = keys[i], bb = keys[ixj];
                    bool desc = ((i & k) == 0);
                    if (desc ? (a < bb) : (a > bb)) { keys[i] = bb; keys[ixj] = a; }
                }
            }
            __syncthreads();
        }
    }
    if (tid < DETS) {
        unsigned long long k = keys[tid];
        int flat = (int)(0xFFFFFFFFu - (unsigned int)(k & 0xFFFFFFFFu));
        float* o = out + tid * 9;
        const float* bx = &g_obox[flat * 7];
#pragma unroll
        for (int q = 0; q < 7; q++) o[q] = bx[q];
        o[7] = g_keep[flat] ? g_vals[flat] : -1e9f;
        o[8] = (float)((flat >> 9) + 1);
    }
}

// ---------------- launcher --------------------------------------------------
extern "C" void kernel_launch(void* const* d_in, const int* in_sizes, int n_in,
                              void* d_out, int out_size) {
    const float* logits = (const float*)d_in[0];
    const float* breg   = (const float*)d_in[1];
    const float* props  = (const float*)d_in[2];
    int N = in_sizes[2] / 7;

    cudaFuncSetAttribute(select_kernel,
                         cudaFuncAttributeMaxDynamicSharedMemorySize, 65536);

    zero_kernel<<<160, 256>>>();
    hist_kernel<<<(N + 255) / 256, 256>>>(logits, N);
    cutoff_kernel<<<FG, 512>>>();
    collect_kernel<<<(N + 255) / 256, 256>>>(logits, N);
    select_kernel<<<FG, 512, 65536>>>(breg, props);
    iou_kernel<<<dim3(8, FG), 512>>>();
    nms_kernel<<<FG, 512>>>();
    final_kernel<<<1, 1024>>>((float*)d_out);
}